// round 14
// baseline (speedup 1.0000x reference)
#include <cuda_runtime.h>
#include <cuda_bf16.h>
#include <cstdint>
#include <math.h>

#define PB 2
#define PS 2048
#define PD 1024
#define PH 16
#define PDK 64

__device__ float g_Q[PB * PH * PS * PDK];
__device__ float g_K[PB * PH * PS * PDK];
__device__ float g_V[PB * PH * PS * PDK];
__device__ int g_mask_flag;

__device__ __nv_bfloat16 g_Ah[3 * 4096 * 1024];
__device__ __nv_bfloat16 g_Al[3 * 4096 * 1024];
__device__ __nv_bfloat16 g_Wqh[1024 * 1024];
__device__ __nv_bfloat16 g_Wql[1024 * 1024];
__device__ __nv_bfloat16 g_Woh[1024 * 1024];
__device__ __nv_bfloat16 g_Wol[1024 * 1024];
__device__ __nv_bfloat16 g_Oh[4096 * 1024];
__device__ __nv_bfloat16 g_Ol[4096 * 1024];

__device__ __forceinline__ uint32_t smem_u32(const void* p) {
    uint32_t a;
    asm("{ .reg .u64 t; cvta.to.shared.u64 t, %1; cvt.u32.u64 %0, t; }"
        : "=r"(a) : "l"(p));
    return a;
}

__device__ __forceinline__ uint32_t f2tf32(float f) {
    uint32_t r;
    asm("cvt.rna.tf32.f32 %0, %1;" : "=r"(r) : "f"(f));
    return r;
}

__device__ __forceinline__ void mma8(float* c, const uint32_t* a, uint32_t b0, uint32_t b1) {
    asm volatile(
        "mma.sync.aligned.m16n8k8.row.col.f32.tf32.tf32.f32 "
        "{%0,%1,%2,%3}, {%4,%5,%6,%7}, {%8,%9}, {%0,%1,%2,%3};"
        : "+f"(c[0]), "+f"(c[1]), "+f"(c[2]), "+f"(c[3])
        : "r"(a[0]), "r"(a[1]), "r"(a[2]), "r"(a[3]), "r"(b0), "r"(b1));
}

__device__ __forceinline__ void mma16(float* c, const uint32_t* a, uint32_t b0, uint32_t b1) {
    asm volatile(
        "mma.sync.aligned.m16n8k16.row.col.f32.bf16.bf16.f32 "
        "{%0,%1,%2,%3}, {%4,%5,%6,%7}, {%8,%9}, {%0,%1,%2,%3};"
        : "+f"(c[0]), "+f"(c[1]), "+f"(c[2]), "+f"(c[3])
        : "r"(a[0]), "r"(a[1]), "r"(a[2]), "r"(a[3]), "r"(b0), "r"(b1));
}

#define CP16(dst_u32, src_ptr) \
    asm volatile("cp.async.cg.shared.global [%0], [%1], 16;" :: "r"(dst_u32), "l"(src_ptr))
#define CP_COMMIT() asm volatile("cp.async.commit_group;" ::: "memory")
#define CP_WAIT0() asm volatile("cp.async.wait_group 0;" ::: "memory")

__global__ void mask_reset_kernel() { g_mask_flag = 1; }

__global__ void mask_scan_kernel(const int4* __restrict__ m, int n4) {
    int idx = blockIdx.x * blockDim.x + threadIdx.x;
    int stride = gridDim.x * blockDim.x;
    bool z = false;
    for (int i = idx; i < n4; i += stride) {
        int4 v = m[i];
        if (!(v.x && v.y && v.z && v.w)) z = true;
    }
    if (z) atomicAnd(&g_mask_flag, 0);
}

__global__ void split_pair_kernel(const float* __restrict__ src,
                                  __nv_bfloat16* __restrict__ hi,
                                  __nv_bfloat16* __restrict__ lo, int n2) {
    int i = blockIdx.x * blockDim.x + threadIdx.x;
    int stride = gridDim.x * blockDim.x;
    for (; i < n2; i += stride) {
        float2 f = ((const float2*)src)[i];
        __nv_bfloat162 h = __floats2bfloat162_rn(f.x, f.y);
        float hx = __bfloat162float(h.x), hy = __bfloat162float(h.y);
        __nv_bfloat162 l = __floats2bfloat162_rn(f.x - hx, f.y - hy);
        ((__nv_bfloat162*)hi)[i] = h;
        ((__nv_bfloat162*)lo)[i] = l;
    }
}

// ---------------------------------------------------------------------------
// bf16x3 GEMM — VERBATIM from the 660us R5 baseline (k-chunk 64, wait0).
// ---------------------------------------------------------------------------
#define GEMM_SMEM (4 * 128 * 36 * 4)

template <int MODE>
__global__ __launch_bounds__(256, 2) void gemm_bf16_kernel(
    const __nv_bfloat16* __restrict__ AhG, const __nv_bfloat16* __restrict__ AlG,
    const __nv_bfloat16* __restrict__ WhG, const __nv_bfloat16* __restrict__ WlG,
    float* __restrict__ outp) {
    extern __shared__ uint32_t smu[];
    uint32_t* Ah = smu;
    uint32_t* Al = Ah + 128 * 36;
    uint32_t* Wh = Al + 128 * 36;
    uint32_t* Wl = Wh + 128 * 36;
    const uint32_t sAh = smem_u32(Ah), sAl = smem_u32(Al);
    const uint32_t sWh = smem_u32(Wh), sWl = smem_u32(Wl);

    const int tid = threadIdx.x;
    const int wid = tid >> 5;
    const int lane = tid & 31;
    const int g = lane >> 2;
    const int tig = lane & 3;

    const int n0 = blockIdx.x * 128;
    const int m0 = blockIdx.y * 128;
    const int m0w = (wid & 1) * 64;
    const int n0w = (wid >> 1) * 32;

    float* C;
    if (MODE == 0) {
        C = (blockIdx.z == 0) ? g_Q : (blockIdx.z == 1) ? g_K : g_V;
    } else {
        C = outp;
    }
    const int zoff = (MODE == 0) ? (int)blockIdx.z * 4096 * 1024 : 0;

    int offA[4], offW[4];
    uint32_t sdst[4];
#pragma unroll
    for (int i = 0; i < 4; i++) {
        int slot = tid + i * 256;
        int row = slot >> 3;
        int seg = slot & 7;
        sdst[i] = (uint32_t)(row * 36 + seg * 4) * 4;
        offW[i] = (n0 + row) * 1024 + seg * 8;
        if (MODE == 0) {
            offA[i] = zoff + (m0 + row) * 1024 + seg * 8;
        } else {
            int m = m0 + row, bb = m >> 11, s = m & 2047;
            offA[i] = ((bb * 16) * 2048 + s) * 64 + seg * 8;
        }
    }
    const int dA = (MODE == 0) ? 64 : (2048 * 64);

    float acc[4][4][4];
#pragma unroll
    for (int i = 0; i < 4; i++)
#pragma unroll
        for (int j = 0; j < 4; j++)
#pragma unroll
            for (int r = 0; r < 4; r++) acc[i][j][r] = 0.0f;

    for (int c = 0; c < 16; c++) {
#pragma unroll
        for (int i = 0; i < 4; i++) {
            CP16(sAh + sdst[i], AhG + offA[i] + c * dA);
            CP16(sAl + sdst[i], AlG + offA[i] + c * dA);
            CP16(sWh + sdst[i], WhG + offW[i] + c * 64);
            CP16(sWl + sdst[i], WlG + offW[i] + c * 64);
        }
        CP_COMMIT();
        CP_WAIT0();
        __syncthreads();

#pragma unroll
        for (int ks = 0; ks < 4; ks++) {
            const int kk = ks * 8;
            uint32_t ah[4][4], alr[4][4];
#pragma unroll
            for (int mf = 0; mf < 4; mf++) {
                int r0 = (m0w + mf * 16 + g) * 36 + kk;
                int r1 = r0 + 8 * 36;
                ah[mf][0] = Ah[r0 + tig];
                ah[mf][1] = Ah[r1 + tig];
                ah[mf][2] = Ah[r0 + tig + 4];
                ah[mf][3] = Ah[r1 + tig + 4];
                alr[mf][0] = Al[r0 + tig];
                alr[mf][1] = Al[r1 + tig];
                alr[mf][2] = Al[r0 + tig + 4];
                alr[mf][3] = Al[r1 + tig + 4];
            }
#pragma unroll
            for (int nf = 0; nf < 4; nf++) {
                int rn = (n0w + nf * 8 + g) * 36 + kk;
                uint32_t bh0 = Wh[rn + tig], bh1 = Wh[rn + tig + 4];
                uint32_t bl0 = Wl[rn + tig], bl1 = Wl[rn + tig + 4];
#pragma unroll
                for (int mf = 0; mf < 4; mf++) {
                    mma16(acc[mf][nf], ah[mf], bh0, bh1);
                    mma16(acc[mf][nf], ah[mf], bl0, bl1);
                    mma16(acc[mf][nf], alr[mf], bh0, bh1);
                }
            }
        }
        __syncthreads();
    }

#pragma unroll
    for (int mf = 0; mf < 4; mf++) {
#pragma unroll
        for (int nf = 0; nf < 4; nf++) {
            int col = n0 + n0w + nf * 8 + 2 * tig;
            int row0 = m0 + m0w + mf * 16 + g;
            int row1 = row0 + 8;
            if (MODE == 0) {
                int h = col >> 6, dk = col & 63;
                int bb0 = row0 >> 11, s0 = row0 & 2047;
                int bb1 = row1 >> 11, s1 = row1 & 2047;
                *(float2*)&C[(((bb0 << 4) + h) * 2048 + s0) * 64 + dk] =
                    make_float2(acc[mf][nf][0], acc[mf][nf][1]);
                *(float2*)&C[(((bb1 << 4) + h) * 2048 + s1) * 64 + dk] =
                    make_float2(acc[mf][nf][2], acc[mf][nf][3]);
            } else {
                *(float2*)&C[row0 * 1024 + col] =
                    make_float2(acc[mf][nf][0], acc[mf][nf][1]);
                *(float2*)&C[row1 * 1024 + col] =
                    make_float2(acc[mf][nf][2], acc[mf][nf][3]);
            }
        }
    }
}

// ---------------------------------------------------------------------------
// Flash attention, tf32 HMMA. Q fragments in registers (loaded once); P fed
// to the PV MMA via quad shuffles (no SMEM round-trip, 2 barriers/tile).
// SMEM: Ks[64][68] + Vs[64][72] = 35,840 B.
// ---------------------------------------------------------------------------
#define ATTN_SMEM ((64 * 68 + 64 * 72) * 4)

__global__ __launch_bounds__(128, 4) void attn_kernel(const int* __restrict__ mask) {
    extern __shared__ float sm[];
    float* Ks = sm;                  // [64][68]; also stages Q pre-loop
    float* Vs = Ks + 64 * 68;        // [64][72]

    const int tid = threadIdx.x;
    const int w = tid >> 5;
    const int lane = tid & 31;
    const int g = lane >> 2;
    const int tig = lane & 3;

    const int q0 = blockIdx.x * 64;
    const int h = blockIdx.y;
    const int b = blockIdx.z;

    const float* Qg = g_Q + (b * 16 + h) * 2048 * 64;
    const float* Kg = g_K + (b * 16 + h) * 2048 * 64;
    const float* Vg = g_V + (b * 16 + h) * 2048 * 64;

    const int rowl0 = w * 16 + g;
    const int rowl1 = rowl0 + 8;

    // Stage Q through Ks region, then pull fragments into registers.
#pragma unroll
    for (int i = 0; i < 8; i++) {
        int slot = tid + i * 128;
        int row = slot >> 4;
        int c4 = (slot & 15) * 4;
        float4 qv = *(const float4*)&Qg[(q0 + row) * 64 + c4];
        Ks[row * 68 + c4 + 0] = __uint_as_float(f2tf32(qv.x));
        Ks[row * 68 + c4 + 1] = __uint_as_float(f2tf32(qv.y));
        Ks[row * 68 + c4 + 2] = __uint_as_float(f2tf32(qv.z));
        Ks[row * 68 + c4 + 3] = __uint_as_float(f2tf32(qv.w));
    }
    __syncthreads();

    uint32_t qa[8][4];
#pragma unroll
    for (int ks = 0; ks < 8; ks++) {
        const int kk = ks * 8;
        qa[ks][0] = __float_as_uint(Ks[rowl0 * 68 + kk + tig]);
        qa[ks][1] = __float_as_uint(Ks[rowl1 * 68 + kk + tig]);
        qa[ks][2] = __float_as_uint(Ks[rowl0 * 68 + kk + tig + 4]);
        qa[ks][3] = __float_as_uint(Ks[rowl1 * 68 + kk + tig + 4]);
    }
    __syncthreads();

    float o[8][4];
#pragma unroll
    for (int nf = 0; nf < 8; nf++)
#pragma unroll
        for (int r = 0; r < 4; r++) o[nf][r] = 0.0f;
    float mprev0 = -1e30f, mprev1 = -1e30f;
    float l0 = 0.0f, l1 = 0.0f;

    const int allones = g_mask_flag;
    const uint32_t srcA = (lane & ~3u) + (tig >> 1);
    const uint32_t srcB = srcA + 2;
    const bool odd = (tig & 1);

    for (int kv0 = 0; kv0 < 2048; kv0 += 64) {
#pragma unroll
        for (int i = 0; i < 8; i++) {
            int slot = tid + i * 128;
            int row = slot >> 4;
            int c4 = (slot & 15) * 4;
            float4 kv = *(const float4*)&Kg[(kv0 + row) * 64 + c4];
            float4 vv = *(const float4*)&Vg[(kv0 + row) * 64 + c4];
            Ks[row * 68 + c4 + 0] = __uint_as_float(f2tf32(kv.x));
            Ks[row * 68 + c4 + 1] = __uint_as_float(f2tf32(kv.y));
            Ks[row * 68 + c4 + 2] = __uint_as_float(f2tf32(kv.z));
            Ks[row * 68 + c4 + 3] = __uint_as_float(f2tf32(kv.w));
            Vs[row * 72 + c4 + 0] = __uint_as_float(f2tf32(vv.x));
            Vs[row * 72 + c4 + 1] = __uint_as_float(f2tf32(vv.y));
            Vs[row * 72 + c4 + 2] = __uint_as_float(f2tf32(vv.z));
            Vs[row * 72 + c4 + 3] = __uint_as_float(f2tf32(vv.w));
        }
        __syncthreads();

        // S = Q @ K^T
        float s[8][4];
#pragma unroll
        for (int nf = 0; nf < 8; nf++)
#pragma unroll
            for (int r = 0; r < 4; r++) s[nf][r] = 0.0f;

#pragma unroll
        for (int ks = 0; ks < 8; ks++) {
            const int kk = ks * 8;
#pragma unroll
            for (int nf = 0; nf < 8; nf++) {
                int rn = (nf * 8 + g) * 68;
                uint32_t b0 = __float_as_uint(Ks[rn + kk + tig]);
                uint32_t b1 = __float_as_uint(Ks[rn + kk + tig + 4]);
                mma8(s[nf], qa[ks], b0, b1);
            }
        }

#pragma unroll
        for (int nf = 0; nf < 8; nf++)
#pragma unroll
            for (int r = 0; r < 4; r++) s[nf][r] *= 0.125f;

        if (!allones) {
            int qr0 = q0 + rowl0, qr1 = q0 + rowl1;
            const int* mb = mask + (long long)b * 2048 * 2048;
#pragma unroll
            for (int nf = 0; nf < 8; nf++) {
                int kc = kv0 + nf * 8 + 2 * tig;
                if (mb[qr0 * 2048 + kc] == 0) s[nf][0] = 1e-9f;
                if (mb[qr0 * 2048 + kc + 1] == 0) s[nf][1] = 1e-9f;
                if (mb[qr1 * 2048 + kc] == 0) s[nf][2] = 1e-9f;
                if (mb[qr1 * 2048 + kc + 1] == 0) s[nf][3] = 1e-9f;
            }
        }

        // Online softmax
        float mx0 = -1e30f, mx1 = -1e30f;
#pragma unroll
        for (int nf = 0; nf < 8; nf++) {
            mx0 = fmaxf(mx0, fmaxf(s[nf][0], s[nf][1]));
            mx1 = fmaxf(mx1, fmaxf(s[nf][2], s[nf][3]));
        }
        mx0 = fmaxf(mx0, __shfl_xor_sync(0xffffffffu, mx0, 1));
        mx0 = fmaxf(mx0, __shfl_xor_sync(0xffffffffu, mx0, 2));
        mx1 = fmaxf(mx1, __shfl_xor_sync(0xffffffffu, mx1, 1));
        mx1 = fmaxf(mx1, __shfl_xor_sync(0xffffffffu, mx1, 2));

        float mnew0 = fmaxf(mprev0, mx0), mnew1 = fmaxf(mprev1, mx1);
        float corr0 = __expf(mprev0 - mnew0), corr1 = __expf(mprev1 - mnew1);
        mprev0 = mnew0; mprev1 = mnew1;

        float rs0 = 0.0f, rs1 = 0.0f;
#pragma unroll
        for (int nf = 0; nf < 8; nf++) {
            s[nf][0] = __expf(s[nf][0] - mnew0);
            s[nf][1] = __expf(s[nf][1] - mnew0);
            s[nf][2] = __expf(s[nf][2] - mnew1);
            s[nf][3] = __expf(s[nf][3] - mnew1);
            rs0 += s[nf][0] + s[nf][1];
            rs1 += s[nf][2] + s[nf][3];
        }
        rs0 += __shfl_xor_sync(0xffffffffu, rs0, 1);
        rs0 += __shfl_xor_sync(0xffffffffu, rs0, 2);
        rs1 += __shfl_xor_sync(0xffffffffu, rs1, 1);
        rs1 += __shfl_xor_sync(0xffffffffu, rs1, 2);
        l0 = l0 * corr0 + rs0;
        l1 = l1 * corr1 + rs1;

#pragma unroll
        for (int nf = 0; nf < 8; nf++) {
            o[nf][0] *= corr0; o[nf][1] *= corr0;
            o[nf][2] *= corr1; o[nf][3] *= corr1;
        }

        // O += P @ V  — P fragments built with quad shuffles (no SMEM).
#pragma unroll
        for (int ks = 0; ks < 8; ks++) {
            const int kk = ks * 8;
            uint32_t p0 = f2tf32(s[ks][0]);
            uint32_t p1 = f2tf32(s[ks][1]);
            uint32_t p2 = f2tf32(s[ks][2]);
            uint32_t p3 = f2tf32(s[ks][3]);
            uint32_t v00 = __shfl_sync(0xffffffffu, p0, srcA);
            uint32_t v01 = __shfl_sync(0xffffffffu, p1, srcA);
            uint32_t v10 = __shfl_sync(0xffffffffu, p2, srcA);
            uint32_t v11 = __shfl_sync(0xffffffffu, p3, srcA);
            uint32_t w00 = __shfl_sync(0xffffffffu, p0, srcB);
            uint32_t w01 = __shfl_sync(0xffffffffu, p1, srcB);
            uint32_t w10 = __shfl_sync(0xffffffffu, p2, srcB);
            uint32_t w11 = __shfl_sync(0xffffffffu, p3, srcB);
            uint32_t a[4];
            a[0] = odd ? v01 : v00;
            a[1] = odd ? v11 : v10;
            a[2] = odd ? w01 : w00;
            a[3] = odd ? w11 : w10;
#pragma unroll
            for (int nf = 0; nf < 8; nf++) {
                uint32_t b0 = __float_as_uint(Vs[(kk + tig) * 72 + nf * 8 + g]);
                uint32_t b1 = __float_as_uint(Vs[(kk + tig + 4) * 72 + nf * 8 + g]);
                mma8(o[nf], a, b0, b1);
            }
        }
        __syncthreads();
    }

    // Normalize + split-store O as bf16 hi/lo
    float inv0 = 1.0f / l0, inv1 = 1.0f / l1;
    const int base0 = ((b * 16 + h) * 2048 + q0 + rowl0) * 64;
    const int base1 = ((b * 16 + h) * 2048 + q0 + rowl1) * 64;
#pragma unroll
    for (int nf = 0; nf < 8; nf++) {
        int col = nf * 8 + 2 * tig;
        float x0 = o[nf][0] * inv0, x1 = o[nf][1] * inv0;
        float y0 = o[nf][2] * inv1, y1 = o[nf][3] * inv1;
        __nv_bfloat162 h0 = __floats2bfloat162_rn(x0, x1);
        __nv_bfloat162 l0p = __floats2bfloat162_rn(x0 - __bfloat162float(h0.x),
                                                   x1 - __bfloat162float(h0.y));
        __nv_bfloat162 h1 = __floats2bfloat162_rn(y0, y1);
        __nv_bfloat162 l1p = __floats2bfloat162_rn(y0 - __bfloat162float(h1.x),
                                                   y1 - __bfloat162float(h1.y));
        *(__nv_bfloat162*)&g_Oh[base0 + col] = h0;
        *(__nv_bfloat162*)&g_Ol[base0 + col] = l0p;
        *(__nv_bfloat162*)&g_Oh[base1 + col] = h1;
        *(__nv_bfloat162*)&g_Ol[base1 + col] = l1p;
    }
}

extern "C" void kernel_launch(void* const* d_in, const int* in_sizes, int n_in,
                              void* d_out, int out_size) {
    const float* q = (const float*)d_in[1];
    const float* k = (const float*)d_in[2];
    const float* v = (const float*)d_in[3];
    const int* mask = (const int*)d_in[4];
    const float* Wq = (const float*)d_in[5];
    const float* Wo = (const float*)d_in[6];
    float* out = (float*)d_out;

    __nv_bfloat16 *ah, *al, *wqh, *wql, *woh, *wol, *oh, *ol;
    cudaGetSymbolAddress((void**)&ah, g_Ah);
    cudaGetSymbolAddress((void**)&al, g_Al);
    cudaGetSymbolAddress((void**)&wqh, g_Wqh);
    cudaGetSymbolAddress((void**)&wql, g_Wql);
    cudaGetSymbolAddress((void**)&woh, g_Woh);
    cudaGetSymbolAddress((void**)&wol, g_Wol);
    cudaGetSymbolAddress((void**)&oh, g_Oh);
    cudaGetSymbolAddress((void**)&ol, g_Ol);

    cudaFuncSetAttribute(attn_kernel, cudaFuncAttributeMaxDynamicSharedMemorySize, ATTN_SMEM);
    cudaFuncSetAttribute(gemm_bf16_kernel<0>, cudaFuncAttributeMaxDynamicSharedMemorySize, GEMM_SMEM);
    cudaFuncSetAttribute(gemm_bf16_kernel<1>, cudaFuncAttributeMaxDynamicSharedMemorySize, GEMM_SMEM);

    mask_reset_kernel<<<1, 1>>>();
    mask_scan_kernel<<<1024, 256>>>((const int4*)mask, PB * PS * PS / 4);

    split_pair_kernel<<<1024, 256>>>(q, ah, al, 4096 * 1024 / 2);
    split_pair_kernel<<<1024, 256>>>(k, ah + 4096 * 1024, al + 4096 * 1024, 4096 * 1024 / 2);
    split_pair_kernel<<<1024, 256>>>(v, ah + 2 * 4096 * 1024, al + 2 * 4096 * 1024, 4096 * 1024 / 2);
    split_pair_kernel<<<512, 256>>>(Wq, wqh, wql, 1024 * 1024 / 2);
    split_pair_kernel<<<512, 256>>>(Wo, woh, wol, 1024 * 1024 / 2);

    gemm_bf16_kernel<0><<<dim3(8, 32, 3), 256, GEMM_SMEM>>>(ah, al, wqh, wql, nullptr);

    attn_kernel<<<dim3(32, 16, 2), 128, ATTN_SMEM>>>(mask);

    gemm_bf16_kernel<1><<<dim3(8, 32, 1), 256, GEMM_SMEM>>>(oh, ol, woh, wol, out);
}

// round 15
// speedup vs baseline: 1.5763x; 1.5763x over previous
#include <cuda_runtime.h>
#include <cuda_bf16.h>
#include <cstdint>
#include <math.h>

#define PB 2
#define PS 2048
#define PD 1024
#define PH 16
#define PDK 64

__device__ float g_Q[PB * PH * PS * PDK];   // tf32-pre-rounded fp32 bits
__device__ float g_K[PB * PH * PS * PDK];
__device__ float g_V[PB * PH * PS * PDK];
__device__ int g_mask_flag;

__device__ __nv_bfloat16 g_Ah[3 * 4096 * 1024];
__device__ __nv_bfloat16 g_Al[3 * 4096 * 1024];
__device__ __nv_bfloat16 g_Wqh[1024 * 1024];
__device__ __nv_bfloat16 g_Wql[1024 * 1024];
__device__ __nv_bfloat16 g_Woh[1024 * 1024];
__device__ __nv_bfloat16 g_Wol[1024 * 1024];
__device__ __nv_bfloat16 g_Oh[4096 * 1024];
__device__ __nv_bfloat16 g_Ol[4096 * 1024];

__device__ __forceinline__ uint32_t smem_u32(const void* p) {
    uint32_t a;
    asm("{ .reg .u64 t; cvta.to.shared.u64 t, %1; cvt.u32.u64 %0, t; }"
        : "=r"(a) : "l"(p));
    return a;
}

__device__ __forceinline__ uint32_t f2tf32(float f) {
    uint32_t r;
    asm("cvt.rna.tf32.f32 %0, %1;" : "=r"(r) : "f"(f));
    return r;
}

__device__ __forceinline__ void mma8(float* c, const uint32_t* a, uint32_t b0, uint32_t b1) {
    asm volatile(
        "mma.sync.aligned.m16n8k8.row.col.f32.tf32.tf32.f32 "
        "{%0,%1,%2,%3}, {%4,%5,%6,%7}, {%8,%9}, {%0,%1,%2,%3};"
        : "+f"(c[0]), "+f"(c[1]), "+f"(c[2]), "+f"(c[3])
        : "r"(a[0]), "r"(a[1]), "r"(a[2]), "r"(a[3]), "r"(b0), "r"(b1));
}

__device__ __forceinline__ void mma16(float* c, const uint32_t* a, uint32_t b0, uint32_t b1) {
    asm volatile(
        "mma.sync.aligned.m16n8k16.row.col.f32.bf16.bf16.f32 "
        "{%0,%1,%2,%3}, {%4,%5,%6,%7}, {%8,%9}, {%0,%1,%2,%3};"
        : "+f"(c[0]), "+f"(c[1]), "+f"(c[2]), "+f"(c[3])
        : "r"(a[0]), "r"(a[1]), "r"(a[2]), "r"(a[3]), "r"(b0), "r"(b1));
}

#define CP16(dst_u32, src_ptr) \
    asm volatile("cp.async.cg.shared.global [%0], [%1], 16;" :: "r"(dst_u32), "l"(src_ptr))
#define CP_COMMIT() asm volatile("cp.async.commit_group;" ::: "memory")
#define CP_WAIT0() asm volatile("cp.async.wait_group 0;" ::: "memory")

__global__ void mask_reset_kernel() { g_mask_flag = 1; }

__global__ void mask_scan_kernel(const int4* __restrict__ m, int n4) {
    int idx = blockIdx.x * blockDim.x + threadIdx.x;
    int stride = gridDim.x * blockDim.x;
    bool z = false;
    for (int i = idx; i < n4; i += stride) {
        int4 v = m[i];
        if (!(v.x && v.y && v.z && v.w)) z = true;
    }
    if (z) atomicAnd(&g_mask_flag, 0);
}

__global__ void split_pair_kernel(const float* __restrict__ src,
                                  __nv_bfloat16* __restrict__ hi,
                                  __nv_bfloat16* __restrict__ lo, int n2) {
    int i = blockIdx.x * blockDim.x + threadIdx.x;
    int stride = gridDim.x * blockDim.x;
    for (; i < n2; i += stride) {
        float2 f = ((const float2*)src)[i];
        __nv_bfloat162 h = __floats2bfloat162_rn(f.x, f.y);
        float hx = __bfloat162float(h.x), hy = __bfloat162float(h.y);
        __nv_bfloat162 l = __floats2bfloat162_rn(f.x - hx, f.y - hy);
        ((__nv_bfloat162*)hi)[i] = h;
        ((__nv_bfloat162*)lo)[i] = l;
    }
}

// ---------------------------------------------------------------------------
// bf16x3 GEMM — R5 baseline. MODE 0 epilogue additionally pre-rounds the
// result to tf32 (bit-identical to what attention would do on load).
// ---------------------------------------------------------------------------
#define GEMM_SMEM (4 * 128 * 36 * 4)

template <int MODE>
__global__ __launch_bounds__(256, 2) void gemm_bf16_kernel(
    const __nv_bfloat16* __restrict__ AhG, const __nv_bfloat16* __restrict__ AlG,
    const __nv_bfloat16* __restrict__ WhG, const __nv_bfloat16* __restrict__ WlG,
    float* __restrict__ outp) {
    extern __shared__ uint32_t smu[];
    uint32_t* Ah = smu;
    uint32_t* Al = Ah + 128 * 36;
    uint32_t* Wh = Al + 128 * 36;
    uint32_t* Wl = Wh + 128 * 36;
    const uint32_t sAh = smem_u32(Ah), sAl = smem_u32(Al);
    const uint32_t sWh = smem_u32(Wh), sWl = smem_u32(Wl);

    const int tid = threadIdx.x;
    const int wid = tid >> 5;
    const int lane = tid & 31;
    const int g = lane >> 2;
    const int tig = lane & 3;

    const int n0 = blockIdx.x * 128;
    const int m0 = blockIdx.y * 128;
    const int m0w = (wid & 1) * 64;
    const int n0w = (wid >> 1) * 32;

    float* C;
    if (MODE == 0) {
        C = (blockIdx.z == 0) ? g_Q : (blockIdx.z == 1) ? g_K : g_V;
    } else {
        C = outp;
    }
    const int zoff = (MODE == 0) ? (int)blockIdx.z * 4096 * 1024 : 0;

    int offA[4], offW[4];
    uint32_t sdst[4];
#pragma unroll
    for (int i = 0; i < 4; i++) {
        int slot = tid + i * 256;
        int row = slot >> 3;
        int seg = slot & 7;
        sdst[i] = (uint32_t)(row * 36 + seg * 4) * 4;
        offW[i] = (n0 + row) * 1024 + seg * 8;
        if (MODE == 0) {
            offA[i] = zoff + (m0 + row) * 1024 + seg * 8;
        } else {
            int m = m0 + row, bb = m >> 11, s = m & 2047;
            offA[i] = ((bb * 16) * 2048 + s) * 64 + seg * 8;
        }
    }
    const int dA = (MODE == 0) ? 64 : (2048 * 64);

    float acc[4][4][4];
#pragma unroll
    for (int i = 0; i < 4; i++)
#pragma unroll
        for (int j = 0; j < 4; j++)
#pragma unroll
            for (int r = 0; r < 4; r++) acc[i][j][r] = 0.0f;

    for (int c = 0; c < 16; c++) {
#pragma unroll
        for (int i = 0; i < 4; i++) {
            CP16(sAh + sdst[i], AhG + offA[i] + c * dA);
            CP16(sAl + sdst[i], AlG + offA[i] + c * dA);
            CP16(sWh + sdst[i], WhG + offW[i] + c * 64);
            CP16(sWl + sdst[i], WlG + offW[i] + c * 64);
        }
        CP_COMMIT();
        CP_WAIT0();
        __syncthreads();

#pragma unroll
        for (int ks = 0; ks < 4; ks++) {
            const int kk = ks * 8;
            uint32_t ah[4][4], alr[4][4];
#pragma unroll
            for (int mf = 0; mf < 4; mf++) {
                int r0 = (m0w + mf * 16 + g) * 36 + kk;
                int r1 = r0 + 8 * 36;
                ah[mf][0] = Ah[r0 + tig];
                ah[mf][1] = Ah[r1 + tig];
                ah[mf][2] = Ah[r0 + tig + 4];
                ah[mf][3] = Ah[r1 + tig + 4];
                alr[mf][0] = Al[r0 + tig];
                alr[mf][1] = Al[r1 + tig];
                alr[mf][2] = Al[r0 + tig + 4];
                alr[mf][3] = Al[r1 + tig + 4];
            }
#pragma unroll
            for (int nf = 0; nf < 4; nf++) {
                int rn = (n0w + nf * 8 + g) * 36 + kk;
                uint32_t bh0 = Wh[rn + tig], bh1 = Wh[rn + tig + 4];
                uint32_t bl0 = Wl[rn + tig], bl1 = Wl[rn + tig + 4];
#pragma unroll
                for (int mf = 0; mf < 4; mf++) {
                    mma16(acc[mf][nf], ah[mf], bh0, bh1);
                    mma16(acc[mf][nf], ah[mf], bl0, bl1);
                    mma16(acc[mf][nf], alr[mf], bh0, bh1);
                }
            }
        }
        __syncthreads();
    }

#pragma unroll
    for (int mf = 0; mf < 4; mf++) {
#pragma unroll
        for (int nf = 0; nf < 4; nf++) {
            int col = n0 + n0w + nf * 8 + 2 * tig;
            int row0 = m0 + m0w + mf * 16 + g;
            int row1 = row0 + 8;
            if (MODE == 0) {
                int h = col >> 6, dk = col & 63;
                int bb0 = row0 >> 11, s0 = row0 & 2047;
                int bb1 = row1 >> 11, s1 = row1 & 2047;
                // tf32 pre-round (bit-identical to attention's former load cvt)
                *(uint2*)&C[(((bb0 << 4) + h) * 2048 + s0) * 64 + dk] =
                    make_uint2(f2tf32(acc[mf][nf][0]), f2tf32(acc[mf][nf][1]));
                *(uint2*)&C[(((bb1 << 4) + h) * 2048 + s1) * 64 + dk] =
                    make_uint2(f2tf32(acc[mf][nf][2]), f2tf32(acc[mf][nf][3]));
            } else {
                *(float2*)&C[row0 * 1024 + col] =
                    make_float2(acc[mf][nf][0], acc[mf][nf][1]);
                *(float2*)&C[row1 * 1024 + col] =
                    make_float2(acc[mf][nf][2], acc[mf][nf][3]);
            }
        }
    }
}

// ---------------------------------------------------------------------------
// Flash attention — R5 structure; staging now pure cp.async (inputs are
// tf32-pre-rounded in GMEM, no per-tile conversion needed).
// SMEM: Qs[64][68] + Ks[64][68](=Ps alias) + Vs[64][72] = 53,248 B.
// ---------------------------------------------------------------------------
#define ATTN_SMEM ((64 * 68 * 2 + 64 * 72) * 4)

__global__ __launch_bounds__(128, 4) void attn_kernel(const int* __restrict__ mask) {
    extern __shared__ float sm[];
    float* Qs = sm;
    float* Ks = Qs + 64 * 68;
    float* Vs = Ks + 64 * 68;
    float* Ps = Ks;
    const uint32_t sQs = smem_u32(Qs);
    const uint32_t sKs = smem_u32(Ks);
    const uint32_t sVs = smem_u32(Vs);

    const int tid = threadIdx.x;
    const int w = tid >> 5;
    const int lane = tid & 31;
    const int g = lane >> 2;
    const int tig = lane & 3;

    const int q0 = blockIdx.x * 64;
    const int h = blockIdx.y;
    const int b = blockIdx.z;

    const float* Qg = g_Q + (b * 16 + h) * 2048 * 64;
    const float* Kg = g_K + (b * 16 + h) * 2048 * 64;
    const float* Vg = g_V + (b * 16 + h) * 2048 * 64;

    // Q tile: cp.async copy (already tf32-rounded bits)
#pragma unroll
    for (int i = 0; i < 8; i++) {
        int slot = tid + i * 128;
        int row = slot >> 4;
        int c4 = (slot & 15) * 4;
        CP16(sQs + (uint32_t)(row * 68 + c4) * 4, Qg + (q0 + row) * 64 + c4);
    }
    CP_COMMIT();

    float o[8][4];
#pragma unroll
    for (int nf = 0; nf < 8; nf++)
#pragma unroll
        for (int r = 0; r < 4; r++) o[nf][r] = 0.0f;
    float mprev0 = -1e30f, mprev1 = -1e30f;
    float l0 = 0.0f, l1 = 0.0f;

    const int allones = g_mask_flag;
    const int rowl0 = w * 16 + g;
    const int rowl1 = rowl0 + 8;

    for (int kv0 = 0; kv0 < 2048; kv0 += 64) {
        // K/V tiles: cp.async copy
#pragma unroll
        for (int i = 0; i < 8; i++) {
            int slot = tid + i * 128;
            int row = slot >> 4;
            int c4 = (slot & 15) * 4;
            CP16(sKs + (uint32_t)(row * 68 + c4) * 4, Kg + (kv0 + row) * 64 + c4);
            CP16(sVs + (uint32_t)(row * 72 + c4) * 4, Vg + (kv0 + row) * 64 + c4);
        }
        CP_COMMIT();
        CP_WAIT0();
        __syncthreads();

        float s[8][4];
#pragma unroll
        for (int nf = 0; nf < 8; nf++)
#pragma unroll
            for (int r = 0; r < 4; r++) s[nf][r] = 0.0f;

#pragma unroll
        for (int ks = 0; ks < 8; ks++) {
            const int kk = ks * 8;
            uint32_t a[4];
            a[0] = __float_as_uint(Qs[rowl0 * 68 + kk + tig]);
            a[1] = __float_as_uint(Qs[rowl1 * 68 + kk + tig]);
            a[2] = __float_as_uint(Qs[rowl0 * 68 + kk + tig + 4]);
            a[3] = __float_as_uint(Qs[rowl1 * 68 + kk + tig + 4]);
#pragma unroll
            for (int nf = 0; nf < 8; nf++) {
                int rn = (nf * 8 + g) * 68;
                uint32_t b0 = __float_as_uint(Ks[rn + kk + tig]);
                uint32_t b1 = __float_as_uint(Ks[rn + kk + tig + 4]);
                mma8(s[nf], a, b0, b1);
            }
        }
        __syncthreads();

#pragma unroll
        for (int nf = 0; nf < 8; nf++)
#pragma unroll
            for (int r = 0; r < 4; r++) s[nf][r] *= 0.125f;

        if (!allones) {
            int qr0 = q0 + rowl0, qr1 = q0 + rowl1;
            const int* mb = mask + (long long)b * 2048 * 2048;
#pragma unroll
            for (int nf = 0; nf < 8; nf++) {
                int kc = kv0 + nf * 8 + 2 * tig;
                if (mb[qr0 * 2048 + kc] == 0) s[nf][0] = 1e-9f;
                if (mb[qr0 * 2048 + kc + 1] == 0) s[nf][1] = 1e-9f;
                if (mb[qr1 * 2048 + kc] == 0) s[nf][2] = 1e-9f;
                if (mb[qr1 * 2048 + kc + 1] == 0) s[nf][3] = 1e-9f;
            }
        }

        float mx0 = -1e30f, mx1 = -1e30f;
#pragma unroll
        for (int nf = 0; nf < 8; nf++) {
            mx0 = fmaxf(mx0, fmaxf(s[nf][0], s[nf][1]));
            mx1 = fmaxf(mx1, fmaxf(s[nf][2], s[nf][3]));
        }
        mx0 = fmaxf(mx0, __shfl_xor_sync(0xffffffffu, mx0, 1));
        mx0 = fmaxf(mx0, __shfl_xor_sync(0xffffffffu, mx0, 2));
        mx1 = fmaxf(mx1, __shfl_xor_sync(0xffffffffu, mx1, 1));
        mx1 = fmaxf(mx1, __shfl_xor_sync(0xffffffffu, mx1, 2));

        float mnew0 = fmaxf(mprev0, mx0), mnew1 = fmaxf(mprev1, mx1);
        float corr0 = __expf(mprev0 - mnew0), corr1 = __expf(mprev1 - mnew1);
        mprev0 = mnew0; mprev1 = mnew1;

        float rs0 = 0.0f, rs1 = 0.0f;
#pragma unroll
        for (int nf = 0; nf < 8; nf++) {
            s[nf][0] = __expf(s[nf][0] - mnew0);
            s[nf][1] = __expf(s[nf][1] - mnew0);
            s[nf][2] = __expf(s[nf][2] - mnew1);
            s[nf][3] = __expf(s[nf][3] - mnew1);
            rs0 += s[nf][0] + s[nf][1];
            rs1 += s[nf][2] + s[nf][3];
        }
        rs0 += __shfl_xor_sync(0xffffffffu, rs0, 1);
        rs0 += __shfl_xor_sync(0xffffffffu, rs0, 2);
        rs1 += __shfl_xor_sync(0xffffffffu, rs1, 1);
        rs1 += __shfl_xor_sync(0xffffffffu, rs1, 2);
        l0 = l0 * corr0 + rs0;
        l1 = l1 * corr1 + rs1;

#pragma unroll
        for (int nf = 0; nf < 8; nf++) {
            o[nf][0] *= corr0; o[nf][1] *= corr0;
            o[nf][2] *= corr1; o[nf][3] *= corr1;
        }

#pragma unroll
        for (int nf = 0; nf < 8; nf++) {
            int pc = nf * 8 + 2 * tig;
            *(uint2*)&Ps[rowl0 * 68 + pc] =
                make_uint2(f2tf32(s[nf][0]), f2tf32(s[nf][1]));
            *(uint2*)&Ps[rowl1 * 68 + pc] =
                make_uint2(f2tf32(s[nf][2]), f2tf32(s[nf][3]));
        }
        __syncthreads();

#pragma unroll
        for (int ks = 0; ks < 8; ks++) {
            const int kk = ks * 8;
            uint32_t a[4];
            a[0] = __float_as_uint(Ps[rowl0 * 68 + kk + tig]);
            a[1] = __float_as_uint(Ps[rowl1 * 68 + kk + tig]);
            a[2] = __float_as_uint(Ps[rowl0 * 68 + kk + tig + 4]);
            a[3] = __float_as_uint(Ps[rowl1 * 68 + kk + tig + 4]);
#pragma unroll
            for (int nf = 0; nf < 8; nf++) {
                uint32_t b0 = __float_as_uint(Vs[(kk + tig) * 72 + nf * 8 + g]);
                uint32_t b1 = __float_as_uint(Vs[(kk + tig + 4) * 72 + nf * 8 + g]);
                mma8(o[nf], a, b0, b1);
            }
        }
        __syncthreads();
    }

    float inv0 = 1.0f / l0, inv1 = 1.0f / l1;
    const int base0 = ((b * 16 + h) * 2048 + q0 + rowl0) * 64;
    const int base1 = ((b * 16 + h) * 2048 + q0 + rowl1) * 64;
#pragma unroll
    for (int nf = 0; nf < 8; nf++) {
        int col = nf * 8 + 2 * tig;
        float x0 = o[nf][0] * inv0, x1 = o[nf][1] * inv0;
        float y0 = o[nf][2] * inv1, y1 = o[nf][3] * inv1;
        __nv_bfloat162 h0 = __floats2bfloat162_rn(x0, x1);
        __nv_bfloat162 l0p = __floats2bfloat162_rn(x0 - __bfloat162float(h0.x),
                                                   x1 - __bfloat162float(h0.y));
        __nv_bfloat162 h1 = __floats2bfloat162_rn(y0, y1);
        __nv_bfloat162 l1p = __floats2bfloat162_rn(y0 - __bfloat162float(h1.x),
                                                   y1 - __bfloat162float(h1.y));
        *(__nv_bfloat162*)&g_Oh[base0 + col] = h0;
        *(__nv_bfloat162*)&g_Ol[base0 + col] = l0p;
        *(__nv_bfloat162*)&g_Oh[base1 + col] = h1;
        *(__nv_bfloat162*)&g_Ol[base1 + col] = l1p;
    }
}

extern "C" void kernel_launch(void* const* d_in, const int* in_sizes, int n_in,
                              void* d_out, int out_size) {
    const float* q = (const float*)d_in[1];
    const float* k = (const float*)d_in[2];
    const float* v = (const float*)d_in[3];
    const int* mask = (const int*)d_in[4];
    const float* Wq = (const float*)d_in[5];
    const float* Wo = (const float*)d_in[6];
    float* out = (float*)d_out;

    __nv_bfloat16 *ah, *al, *wqh, *wql, *woh, *wol, *oh, *ol;
    cudaGetSymbolAddress((void**)&ah, g_Ah);
    cudaGetSymbolAddress((void**)&al, g_Al);
    cudaGetSymbolAddress((void**)&wqh, g_Wqh);
    cudaGetSymbolAddress((void**)&wql, g_Wql);
    cudaGetSymbolAddress((void**)&woh, g_Woh);
    cudaGetSymbolAddress((void**)&wol, g_Wol);
    cudaGetSymbolAddress((void**)&oh, g_Oh);
    cudaGetSymbolAddress((void**)&ol, g_Ol);

    cudaFuncSetAttribute(attn_kernel, cudaFuncAttributeMaxDynamicSharedMemorySize, ATTN_SMEM);
    cudaFuncSetAttribute(gemm_bf16_kernel<0>, cudaFuncAttributeMaxDynamicSharedMemorySize, GEMM_SMEM);
    cudaFuncSetAttribute(gemm_bf16_kernel<1>, cudaFuncAttributeMaxDynamicSharedMemorySize, GEMM_SMEM);

    mask_reset_kernel<<<1, 1>>>();
    mask_scan_kernel<<<1024, 256>>>((const int4*)mask, PB * PS * PS / 4);

    split_pair_kernel<<<1024, 256>>>(q, ah, al, 4096 * 1024 / 2);
    split_pair_kernel<<<1024, 256>>>(k, ah + 4096 * 1024, al + 4096 * 1024, 4096 * 1024 / 2);
    split_pair_kernel<<<1024, 256>>>(v, ah + 2 * 4096 * 1024, al + 2 * 4096 * 1024, 4096 * 1024 / 2);
    split_pair_kernel<<<512, 256>>>(Wq, wqh, wql, 1024 * 1024 / 2);
    split_pair_kernel<<<512, 256>>>(Wo, woh, wol, 1024 * 1024 / 2);

    gemm_bf16_kernel<0><<<dim3(8, 32, 3), 256, GEMM_SMEM>>>(ah, al, wqh, wql, nullptr);

    attn_kernel<<<dim3(32, 16, 2), 128, ATTN_SMEM>>>(mask);

    gemm_bf16_kernel<1><<<dim3(8, 32, 1), 256, GEMM_SMEM>>>(oh, ol, woh, wol, out);
}